// round 14
// baseline (speedup 1.0000x reference)
#include <cuda_runtime.h>
#include <cuda_fp16.h>
#include <math.h>
#include <stdint.h>

// Problem constants
#define BSZ   8
#define NPTS  4096
#define CDIM  128
#define KTOP  9
#define MROWS (BSZ * NPTS)   // 32768
#define EPSBN 1e-5f

// ---------------- scratch (device globals; no allocation allowed) ----------------
__device__ float g_h  [MROWS * CDIM];
__device__ float g_agg[MROWS * CDIM];
__device__ float g_t2 [MROWS * CDIM];
__device__ float g_sq [MROWS];
__device__ __half g_hh[MROWS * CDIM];   // fp16 hi split of h
__device__ __half g_hm[MROWS * CDIM];   // fp16 mid split (residual)
__device__ float g_dist[(size_t)MROWS * NPTS];  // 512MB distance keys
__device__ float g_tmin[(size_t)MROWS * 64];    // per-row per-64col-subtile min
__device__ float g_psum[256 * 128];
__device__ float g_psq [256 * 128];
__device__ float g_mean[128];
__device__ float g_rstd[128];

// =================================================================================
// PTX helpers (baseline sm_80+ ISA only: ldmatrix / mma.sync / cp.async)
// =================================================================================
__device__ __forceinline__ uint32_t smem_u32(const void* p) {
    uint32_t a;
    asm("{ .reg .u64 t; cvta.to.shared.u64 t, %1; cvt.u32.u64 %0, t; }" : "=r"(a) : "l"(p));
    return a;
}
__device__ __forceinline__ void ldsm4(uint32_t* r, uint32_t a) {
    asm volatile("ldmatrix.sync.aligned.m8n8.x4.shared.b16 {%0,%1,%2,%3}, [%4];"
                 : "=r"(r[0]), "=r"(r[1]), "=r"(r[2]), "=r"(r[3]) : "r"(a));
}
__device__ __forceinline__ void mma16816h(float* c, const uint32_t* a, uint32_t b0, uint32_t b1) {
    asm volatile("mma.sync.aligned.m16n8k16.row.col.f32.f16.f16.f32 "
                 "{%0,%1,%2,%3},{%4,%5,%6,%7},{%8,%9},{%0,%1,%2,%3};"
                 : "+f"(c[0]), "+f"(c[1]), "+f"(c[2]), "+f"(c[3])
                 : "r"(a[0]), "r"(a[1]), "r"(a[2]), "r"(a[3]), "r"(b0), "r"(b1));
}
__device__ __forceinline__ void cp16(uint32_t dst, const void* src) {
    asm volatile("cp.async.cg.shared.global [%0], [%1], 16;" :: "r"(dst), "l"(src));
}
#define CP_COMMIT() asm volatile("cp.async.commit_group;" ::: "memory")
#define CP_WAIT(n)  asm volatile("cp.async.wait_group %0;" :: "n"(n) : "memory")

// =================================================================================
// Tiled SGEMM: out[M x 128] = A[M x 128] @ W (+ A2 @ W[128:]) + bias.
// Fused deterministic column stats (sum / sumsq) into the epilogue.
// =================================================================================
__global__ __launch_bounds__(256) void gemm128(const float* __restrict__ A,
                                               const float* __restrict__ A2,
                                               const float* __restrict__ W,
                                               const float* __restrict__ bias,
                                               float* __restrict__ out)
{
    __shared__ float As[32 * 132];
    __shared__ float Ws[32 * 132];
    const int t  = threadIdx.x;
    const int tx = t & 15, ty = t >> 4;
    const int r0 = blockIdx.x * 128;

    float c[8][8];
#pragma unroll
    for (int i = 0; i < 8; i++)
#pragma unroll
        for (int j = 0; j < 8; j++) c[i][j] = 0.f;

    const int nSrc = A2 ? 2 : 1;
    for (int si = 0; si < nSrc; si++) {
        const float* Ap = si ? A2 : A;
        const float* Wp = W + si * 128 * 128;
        for (int kc = 0; kc < 128; kc += 32) {
            __syncthreads();
#pragma unroll
            for (int i = 0; i < 4; i++) {
                int lin = t + i * 256;
                int m = lin >> 3, kq = lin & 7;
                float4 v = *(const float4*)&Ap[(size_t)(r0 + m) * 128 + kc + kq * 4];
                As[(kq * 4 + 0) * 132 + m] = v.x;
                As[(kq * 4 + 1) * 132 + m] = v.y;
                As[(kq * 4 + 2) * 132 + m] = v.z;
                As[(kq * 4 + 3) * 132 + m] = v.w;
            }
#pragma unroll
            for (int i = 0; i < 4; i++) {
                int lin = t + i * 256;
                int k = lin >> 5, n4 = lin & 31;
                float4 v = *(const float4*)&Wp[(size_t)(kc + k) * 128 + n4 * 4];
                *(float4*)&Ws[k * 132 + n4 * 4] = v;
            }
            __syncthreads();
#pragma unroll 8
            for (int k = 0; k < 32; k++) {
                float4 a0 = *(const float4*)&As[k * 132 + ty * 8];
                float4 a1 = *(const float4*)&As[k * 132 + ty * 8 + 4];
                float4 b0 = *(const float4*)&Ws[k * 132 + tx * 8];
                float4 b1 = *(const float4*)&Ws[k * 132 + tx * 8 + 4];
                float a[8] = {a0.x, a0.y, a0.z, a0.w, a1.x, a1.y, a1.z, a1.w};
                float b[8] = {b0.x, b0.y, b0.z, b0.w, b1.x, b1.y, b1.z, b1.w};
#pragma unroll
                for (int i = 0; i < 8; i++)
#pragma unroll
                    for (int j = 0; j < 8; j++) c[i][j] = fmaf(a[i], b[j], c[i][j]);
            }
        }
    }

    float bv[8];
#pragma unroll
    for (int j = 0; j < 8; j++) bv[j] = bias ? bias[tx * 8 + j] : 0.f;

    float s1[8], s2[8];
#pragma unroll
    for (int j = 0; j < 8; j++) { s1[j] = 0.f; s2[j] = 0.f; }

#pragma unroll
    for (int i = 0; i < 8; i++) {
        size_t base = (size_t)(r0 + ty * 8 + i) * 128 + tx * 8;
        float v[8];
#pragma unroll
        for (int j = 0; j < 8; j++) {
            v[j] = c[i][j] + bv[j];
            s1[j] += v[j];
            s2[j] += v[j] * v[j];
        }
        *(float4*)&out[base]     = make_float4(v[0], v[1], v[2], v[3]);
        *(float4*)&out[base + 4] = make_float4(v[4], v[5], v[6], v[7]);
    }

    __syncthreads();
#pragma unroll
    for (int j = 0; j < 8; j++) {
        As[ty * 128 + tx * 8 + j] = s1[j];
        Ws[ty * 128 + tx * 8 + j] = s2[j];
    }
    __syncthreads();
    if (t < 128) {
        float S = 0.f, Q = 0.f;
#pragma unroll
        for (int g = 0; g < 16; g++) { S += As[g * 128 + t]; Q += Ws[g * 128 + t]; }
        g_psum[blockIdx.x * 128 + t] = S;
        g_psq [blockIdx.x * 128 + t] = Q;
    }
}

__global__ void colstat_final()
{
    const int t = threadIdx.x;
    float s = 0.f, s2 = 0.f;
    for (int b = 0; b < 256; b++) { s += g_psum[b * 128 + t]; s2 += g_psq[b * 128 + t]; }
    float m   = s / (float)MROWS;
    float var = s2 / (float)MROWS - m * m;
    g_mean[t] = m;
    g_rstd[t] = rsqrtf(var + EPSBN);
}

// ============ BN apply (mode 1: +GELU, mode 2: +residual) ============
__global__ void bn_apply(const float* __restrict__ X, const float* __restrict__ gamma,
                         const float* __restrict__ beta, const float* __restrict__ resid,
                         float* __restrict__ Y, int mode)
{
    const int i4 = blockIdx.x * blockDim.x + threadIdx.x;
    const size_t i = (size_t)i4 * 4;
    const int ch = (int)(i & 127);
    float4 v  = *(const float4*)&X[i];
    float4 ga = *(const float4*)&gamma[ch];
    float4 be = *(const float4*)&beta[ch];
    float4 mn = *(const float4*)&g_mean[ch];
    float4 rs = *(const float4*)&g_rstd[ch];
    float o[4];
    o[0] = ga.x * (v.x - mn.x) * rs.x + be.x;
    o[1] = ga.y * (v.y - mn.y) * rs.y + be.y;
    o[2] = ga.z * (v.z - mn.z) * rs.z + be.z;
    o[3] = ga.w * (v.w - mn.w) * rs.w + be.w;
    if (mode == 1) {
#pragma unroll
        for (int j = 0; j < 4; j++)
            o[j] = 0.5f * o[j] * (1.f + erff(o[j] * 0.70710678118654752f));
    } else if (mode == 2) {
        float4 r = *(const float4*)&resid[i];
        o[0] += r.x; o[1] += r.y; o[2] += r.z; o[3] += r.w;
    }
    *(float4*)&Y[i] = make_float4(o[0], o[1], o[2], o[3]);
}

// ===== BN apply + fp16 2-way split + row sq-norm (fc1 output), warp per row =====
__global__ void bn_split(const float* __restrict__ X, const float* __restrict__ gamma,
                         const float* __restrict__ beta, float* __restrict__ H,
                         __half* __restrict__ Hh, __half* __restrict__ Hm,
                         float* __restrict__ sqo)
{
    const int wid = threadIdx.x >> 5, lane = threadIdx.x & 31;
    const int row = blockIdx.x * 8 + wid;
    const int ch = lane * 4;
    const size_t base = (size_t)row * 128 + ch;
    float4 v  = *(const float4*)&X[base];
    float4 ga = *(const float4*)&gamma[ch];
    float4 be = *(const float4*)&beta[ch];
    float4 mn = *(const float4*)&g_mean[ch];
    float4 rs = *(const float4*)&g_rstd[ch];
    float o[4];
    o[0] = ga.x * (v.x - mn.x) * rs.x + be.x;
    o[1] = ga.y * (v.y - mn.y) * rs.y + be.y;
    o[2] = ga.z * (v.z - mn.z) * rs.z + be.z;
    o[3] = ga.w * (v.w - mn.w) * rs.w + be.w;
    *(float4*)&H[base] = make_float4(o[0], o[1], o[2], o[3]);

    __half hh[4], hm[4];
#pragma unroll
    for (int j = 0; j < 4; j++) {
        hh[j] = __float2half_rn(o[j]);
        hm[j] = __float2half_rn(o[j] - __half2float(hh[j]));
    }
    ((__half2*)(Hh + base))[0] = __halves2half2(hh[0], hh[1]);
    ((__half2*)(Hh + base))[1] = __halves2half2(hh[2], hh[3]);
    ((__half2*)(Hm + base))[0] = __halves2half2(hm[0], hm[1]);
    ((__half2*)(Hm + base))[1] = __halves2half2(hm[2], hm[3]);

    float s = o[0]*o[0] + o[1]*o[1] + o[2]*o[2] + o[3]*o[3];
#pragma unroll
    for (int off = 16; off; off >>= 1) s += __shfl_xor_sync(0xffffffffu, s, off);
    if (lane == 0) sqo[row] = s;
}

// =================================================================================
// Kernel A: distance GEMM (fp16 2-split, 3 products). Writes keys sq[j]-2*dot to
// g_dist and the per-row per-64-col min to g_tmin. 512 threads, Q resident,
// 2-slot ring, NO selection -> clean MMA pipeline.
// =================================================================================
#define A_ROWB   272
#define A_SPLIT  (128 * A_ROWB)          // 34816
#define A_QBYTES (2 * A_SPLIT)           // 69632
#define A_CBUF   (2 * A_SPLIT)           // 69632 per ring slot (2 splits)
#define A_RING   A_QBYTES
#define A_SQN    (A_RING + 2 * A_CBUF)   // 208896 (2 slots x 512B)
#define A_SMEM   (A_SQN + 1024)          // 209920

// one 128-row x 2-split tile: 4096 cp16 ops, 512 threads -> 8 iters
__device__ __forceinline__ void loadT(uint32_t smdst,
                                      const __half* __restrict__ Hh,
                                      const __half* __restrict__ Hm,
                                      int rowBase, int t)
{
#pragma unroll
    for (int i = 0; i < 8; i++) {
        int lin = t + i * 512;            // [0,4096)
        int s = lin >> 11, rem = lin & 2047;
        int row = rem >> 4, ch = rem & 15;
        const __half* sp = s ? Hm : Hh;
        cp16(smdst + (uint32_t)(s * A_SPLIT + row * A_ROWB + ch * 16),
             (const char*)(sp + (size_t)(rowBase + row) * 128) + ch * 16);
    }
}

__global__ __launch_bounds__(512, 1) void dist_gemm(const __half* __restrict__ Hh,
                                                    const __half* __restrict__ Hm,
                                                    const float* __restrict__ sq,
                                                    float* __restrict__ dist,
                                                    float* __restrict__ tmin)
{
    extern __shared__ __align__(16) char smp[];
    const uint32_t smb = smem_u32(smp);
    const int t = threadIdx.x, w = t >> 5, lane = t & 31;
    const int wr = w & 7;          // 16-row strip
    const int wc = w >> 3;         // 64-col half of the 128-col tile
    const int b = blockIdx.y, bOff = b * NPTS, r0 = blockIdx.x * 128;

    loadT(smb, Hh, Hm, bOff + r0, t);                 // Q resident
    loadT(smb + A_RING, Hh, Hm, bOff, t);             // tile 0
    if (t < 32) cp16(smb + (uint32_t)(A_SQN + t * 16), (const char*)(sq + bOff) + t * 16);
    CP_COMMIT();
    CP_WAIT(0);
    __syncthreads();

    const uint32_t aoff = (uint32_t)((wr * 16 + (lane & 15)) * A_ROWB + ((lane >> 4) * 16));
    const uint32_t boff = (uint32_t)(((lane & 7) + ((lane & 16) ? 8 : 0)) * A_ROWB
                                     + ((lane & 8) ? 16 : 0));
    const int c4 = (lane & 3) * 2;
    const size_t growA = (size_t)(bOff + r0 + wr * 16 + (lane >> 2));
    const size_t growB = growA + 8;

    for (int ct = 0; ct < 32; ct++) {
        if (ct > 0) { CP_WAIT(0); __syncthreads(); }
        if (ct + 1 < 32) {
            loadT(smb + (uint32_t)(A_RING + ((ct + 1) & 1) * A_CBUF), Hh, Hm,
                  bOff + (ct + 1) * 128, t);
            if (t < 32) cp16(smb + (uint32_t)(A_SQN + ((ct + 1) & 1) * 512 + t * 16),
                             (const char*)(sq + bOff + (ct + 1) * 128) + t * 16);
            CP_COMMIT();
        }

        const uint32_t cb = smb + (uint32_t)(A_RING + (ct & 1) * A_CBUF)
                          + (uint32_t)(wc * 64 * A_ROWB);

        float acc[8][4];
#pragma unroll
        for (int n8 = 0; n8 < 8; n8++)
#pragma unroll
            for (int q = 0; q < 4; q++) acc[n8][q] = 0.f;

#pragma unroll
        for (int ks = 0; ks < 8; ks++) {
            uint32_t Af0[4], Af1[4];
            ldsm4(Af0, smb + (uint32_t)(ks * 32) + aoff);
            ldsm4(Af1, smb + (uint32_t)(A_SPLIT + ks * 32) + aoff);
#pragma unroll
            for (int np = 0; np < 4; np++) {
                uint32_t Bh[4], Bm[4];
                ldsm4(Bh, cb + (uint32_t)(np * 16 * A_ROWB + ks * 32) + boff);
                ldsm4(Bm, cb + (uint32_t)(A_SPLIT + np * 16 * A_ROWB + ks * 32) + boff);
                mma16816h(acc[np * 2 + 0], Af0, Bh[0], Bh[1]);   // hh
                mma16816h(acc[np * 2 + 1], Af0, Bh[2], Bh[3]);
                mma16816h(acc[np * 2 + 0], Af0, Bm[0], Bm[1]);   // h*m
                mma16816h(acc[np * 2 + 1], Af0, Bm[2], Bm[3]);
                mma16816h(acc[np * 2 + 0], Af1, Bh[0], Bh[1]);   // m*h
                mma16816h(acc[np * 2 + 1], Af1, Bh[2], Bh[3]);
            }
        }

        // epilogue: keys + stores + per-row subtile min
        const float* sqt = (const float*)(smp + A_SQN + (ct & 1) * 512) + wc * 64;
        const int col0 = ct * 128 + wc * 64;
        float mnA = 3.0e38f, mnB = 3.0e38f;
#pragma unroll
        for (int n8 = 0; n8 < 8; n8++) {
            const int cc = (n8 >> 1) * 16 + (n8 & 1) * 8 + c4;
            float s0 = sqt[cc], s1 = sqt[cc + 1];
            float kA0 = fmaf(-2.f, acc[n8][0], s0);
            float kA1 = fmaf(-2.f, acc[n8][1], s1);
            float kB0 = fmaf(-2.f, acc[n8][2], s0);
            float kB1 = fmaf(-2.f, acc[n8][3], s1);
            mnA = fminf(mnA, fminf(kA0, kA1));
            mnB = fminf(mnB, fminf(kB0, kB1));
            *(float2*)&dist[growA * NPTS + col0 + cc] = make_float2(kA0, kA1);
            *(float2*)&dist[growB * NPTS + col0 + cc] = make_float2(kB0, kB1);
        }
        mnA = fminf(mnA, __shfl_xor_sync(0xffffffffu, mnA, 1));
        mnA = fminf(mnA, __shfl_xor_sync(0xffffffffu, mnA, 2));
        mnB = fminf(mnB, __shfl_xor_sync(0xffffffffu, mnB, 1));
        mnB = fminf(mnB, __shfl_xor_sync(0xffffffffu, mnB, 2));
        if ((lane & 3) == 0) {
            tmin[growA * 64 + ct * 2 + wc] = mnA;
            tmin[growB * 64 + ct * 2 + wc] = mnB;
        }
    }
}

// =================================================================================
// Kernel B: pruned top-9 selection + gather + max-relative aggregation.
// Block 256 thr = 8 warps, warp per row. M9 = 9th-smallest of 64 subtile mins
// bounds the 9th-best key; subtiles with min > M9 are skipped (provably safe).
// =================================================================================
// register insertion into sorted top-9 (strict <, stable for ascending-j feed)
#define INS9(Bst, Idx, KEY, J) do {                                        \
    float _k = (KEY); int _j = (J);                                        \
    if (_k < Bst[8]) {                                                     \
        float ck = _k; int cj = _j;                                        \
        _Pragma("unroll")                                                  \
        for (int _p = 0; _p < 9; _p++) {                                   \
            if (ck < Bst[_p]) {                                            \
                float tk = Bst[_p]; int tj = Idx[_p];                      \
                Bst[_p] = ck; Idx[_p] = cj; ck = tk; cj = tj;              \
            }                                                              \
        }                                                                  \
    }                                                                      \
} while (0)

__global__ __launch_bounds__(256, 4) void knn_select(const float* __restrict__ dist,
                                                     const float* __restrict__ tmin,
                                                     const float* __restrict__ h,
                                                     float* __restrict__ agg)
{
    __shared__ float tms[8][64];
    __shared__ float mks[8][32 * 9];
    __shared__ int   mis[8][32 * 9];
    __shared__ float m9s[8];
    __shared__ int   nbx[8][12];

    const int t = threadIdx.x, w = t >> 5, lane = t & 31;
    const int row = blockIdx.x * 8 + w;      // global row
    const int b = row >> 12;
    const size_t rbase = (size_t)row * NPTS;

    tms[w][lane]      = tmin[(size_t)row * 64 + lane];
    tms[w][lane + 32] = tmin[(size_t)row * 64 + lane + 32];
    __syncwarp();
    if (lane == 0) {
        float m[9];
#pragma unroll
        for (int p = 0; p < 9; p++) m[p] = 3.0e38f;
        for (int q = 0; q < 64; q++) {
            float k = tms[w][q];
            if (k < m[8]) {
                float ck = k;
#pragma unroll
                for (int p = 0; p < 9; p++)
                    if (ck < m[p]) { float tk = m[p]; m[p] = ck; ck = tk; }
            }
        }
        m9s[w] = m[8];
    }
    __syncwarp();
    const float M9 = m9s[w];

    float bst[9]; int idx[9];
#pragma unroll
    for (int p = 0; p < 9; p++) { bst[p] = 3.0e38f; idx[p] = 0; }

    for (int sub = 0; sub < 64; sub++) {
        if (tms[w][sub] > M9) continue;      // provably no top-9 member here
        float2 kk = *(const float2*)&dist[rbase + sub * 64 + lane * 2];
        int j = sub * 64 + lane * 2;
        INS9(bst, idx, kk.x, j);
        INS9(bst, idx, kk.y, j + 1);
    }

#pragma unroll
    for (int p = 0; p < 9; p++) { mks[w][lane * 9 + p] = bst[p]; mis[w][lane * 9 + p] = idx[p]; }
    __syncthreads();

    if (t < 8) {
        float bk[9]; int bj[9];
#pragma unroll
        for (int p = 0; p < 9; p++) { bk[p] = 3.0e38f; bj[p] = 0x7fffffff; }
        for (int l = 0; l < 32; l++) {
            for (int p = 0; p < 9; p++) {
                float k = mks[t][l * 9 + p];
                if (k > bk[8]) break;        // per-lane list ascending -> safe
                int j = mis[t][l * 9 + p];
                if (k < bk[8] || (k == bk[8] && j < bj[8])) {
                    float ck = k; int cj = j;
#pragma unroll
                    for (int pp = 0; pp < 9; pp++) {
                        if (ck < bk[pp] || (ck == bk[pp] && cj < bj[pp])) {
                            float tk = bk[pp]; int tj = bj[pp];
                            bk[pp] = ck; bj[pp] = cj; ck = tk; cj = tj;
                        }
                    }
                }
            }
        }
#pragma unroll
        for (int p = 0; p < 9; p++) nbx[t][p] = bj[p];
    }
    __syncthreads();

    // gather + max-relative aggregation (warp handles its own row)
    float4 q = *(const float4*)&h[(size_t)row * 128 + lane * 4];
    float m0 = -3.0e38f, m1 = -3.0e38f, m2 = -3.0e38f, m3 = -3.0e38f;
#pragma unroll
    for (int p = 0; p < KTOP; p++) {
        int j = nbx[w][p];
        float4 v = *(const float4*)&h[(size_t)(b * NPTS + j) * 128 + lane * 4];
        m0 = fmaxf(m0, v.x); m1 = fmaxf(m1, v.y);
        m2 = fmaxf(m2, v.z); m3 = fmaxf(m3, v.w);
    }
    *(float4*)&agg[(size_t)row * 128 + lane * 4] =
        make_float4(m0 - q.x, m1 - q.y, m2 - q.z, m3 - q.w);
}

// =================================================================================
// Launch sequence
// =================================================================================
extern "C" void kernel_launch(void* const* d_in, const int* in_sizes, int n_in,
                              void* d_out, int out_size)
{
    const float* x   = (const float*)d_in[0];
    const float* W1  = (const float*)d_in[1];
    const float* b1  = (const float*)d_in[2];
    const float* g1  = (const float*)d_in[3];
    const float* be1 = (const float*)d_in[4];
    const float* Wg  = (const float*)d_in[5];
    const float* bg  = (const float*)d_in[6];
    const float* gg  = (const float*)d_in[7];
    const float* beg = (const float*)d_in[8];
    const float* W2  = (const float*)d_in[9];
    const float* b2  = (const float*)d_in[10];
    const float* g2  = (const float*)d_in[11];
    const float* be2 = (const float*)d_in[12];
    float* out = (float*)d_out;

    float *ph, *pagg, *pt2, *psq, *pdist, *ptmin;
    __half *phh, *phm;
    cudaGetSymbolAddress((void**)&ph,   g_h);
    cudaGetSymbolAddress((void**)&pagg, g_agg);
    cudaGetSymbolAddress((void**)&pt2,  g_t2);
    cudaGetSymbolAddress((void**)&psq,  g_sq);
    cudaGetSymbolAddress((void**)&phh,  g_hh);
    cudaGetSymbolAddress((void**)&phm,  g_hm);
    cudaGetSymbolAddress((void**)&pdist, g_dist);
    cudaGetSymbolAddress((void**)&ptmin, g_tmin);

    cudaFuncSetAttribute(dist_gemm, cudaFuncAttributeMaxDynamicSharedMemorySize, A_SMEM);

    // fc1 (+fused stats) + BN/split/norms
    gemm128<<<256, 256>>>(x, nullptr, W1, b1, ph);
    colstat_final<<<1, 128>>>();
    bn_split<<<4096, 256>>>(ph, g1, be1, ph, phh, phm, psq);

    // KNN: distance GEMM -> pruned selection + aggregation
    dist_gemm<<<dim3(32, 8), 512, A_SMEM>>>(phh, phm, psq, pdist, ptmin);
    knn_select<<<4096, 256>>>(pdist, ptmin, ph, pagg);

    // graph conv MLP: cat([h, agg]) @ Wg + bg (single fused 256-K GEMM), BN, GELU
    gemm128<<<256, 256>>>(ph, pagg, Wg, bg, pt2);
    colstat_final<<<1, 128>>>();
    bn_apply<<<4096, 256>>>(pt2, gg, beg, nullptr, pt2, 1);

    // fc2 (+fused stats) + BN + residual
    gemm128<<<256, 256>>>(pt2, nullptr, W2, b2, out);
    colstat_final<<<1, 128>>>();
    bn_apply<<<4096, 256>>>(out, g2, be2, x, out, 2);
}

// round 15
// speedup vs baseline: 1.7295x; 1.7295x over previous
#include <cuda_runtime.h>
#include <cuda_fp16.h>
#include <math.h>
#include <stdint.h>

// Problem constants
#define BSZ   8
#define NPTS  4096
#define CDIM  128
#define KTOP  9
#define MROWS (BSZ * NPTS)   // 32768
#define EPSBN 1e-5f

// ---------------- scratch (device globals; no allocation allowed) ----------------
__device__ float g_h  [MROWS * CDIM];
__device__ float g_agg[MROWS * CDIM];
__device__ float g_t2 [MROWS * CDIM];
__device__ float g_sq [MROWS];
__device__ __half g_hh[MROWS * CDIM];   // fp16 hi split of h
__device__ __half g_hm[MROWS * CDIM];   // fp16 mid split (residual)
__device__ float g_psum[256 * 128];
__device__ float g_psq [256 * 128];
__device__ float g_mean[128];
__device__ float g_rstd[128];

// =================================================================================
// PTX helpers (baseline sm_80+ ISA only: ldmatrix / mma.sync / cp.async)
// =================================================================================
__device__ __forceinline__ uint32_t smem_u32(const void* p) {
    uint32_t a;
    asm("{ .reg .u64 t; cvta.to.shared.u64 t, %1; cvt.u32.u64 %0, t; }" : "=r"(a) : "l"(p));
    return a;
}
__device__ __forceinline__ void ldsm4(uint32_t* r, uint32_t a) {
    asm volatile("ldmatrix.sync.aligned.m8n8.x4.shared.b16 {%0,%1,%2,%3}, [%4];"
                 : "=r"(r[0]), "=r"(r[1]), "=r"(r[2]), "=r"(r[3]) : "r"(a));
}
__device__ __forceinline__ void mma16816h(float* c, const uint32_t* a, uint32_t b0, uint32_t b1) {
    asm volatile("mma.sync.aligned.m16n8k16.row.col.f32.f16.f16.f32 "
                 "{%0,%1,%2,%3},{%4,%5,%6,%7},{%8,%9},{%0,%1,%2,%3};"
                 : "+f"(c[0]), "+f"(c[1]), "+f"(c[2]), "+f"(c[3])
                 : "r"(a[0]), "r"(a[1]), "r"(a[2]), "r"(a[3]), "r"(b0), "r"(b1));
}
__device__ __forceinline__ void cp16(uint32_t dst, const void* src) {
    asm volatile("cp.async.cg.shared.global [%0], [%1], 16;" :: "r"(dst), "l"(src));
}
#define CP_COMMIT() asm volatile("cp.async.commit_group;" ::: "memory")
#define CP_WAIT(n)  asm volatile("cp.async.wait_group %0;" :: "n"(n) : "memory")

// =================================================================================
// Tiled SGEMM: out[M x 128] = A[M x 128] @ W (+ A2 @ W[128:]) + bias.
// Fused deterministic column stats (sum / sumsq) into the epilogue.
// =================================================================================
__global__ __launch_bounds__(256) void gemm128(const float* __restrict__ A,
                                               const float* __restrict__ A2,
                                               const float* __restrict__ W,
                                               const float* __restrict__ bias,
                                               float* __restrict__ out)
{
    __shared__ float As[32 * 132];
    __shared__ float Ws[32 * 132];
    const int t  = threadIdx.x;
    const int tx = t & 15, ty = t >> 4;
    const int r0 = blockIdx.x * 128;

    float c[8][8];
#pragma unroll
    for (int i = 0; i < 8; i++)
#pragma unroll
        for (int j = 0; j < 8; j++) c[i][j] = 0.f;

    const int nSrc = A2 ? 2 : 1;
    for (int si = 0; si < nSrc; si++) {
        const float* Ap = si ? A2 : A;
        const float* Wp = W + si * 128 * 128;
        for (int kc = 0; kc < 128; kc += 32) {
            __syncthreads();
#pragma unroll
            for (int i = 0; i < 4; i++) {
                int lin = t + i * 256;
                int m = lin >> 3, kq = lin & 7;
                float4 v = *(const float4*)&Ap[(size_t)(r0 + m) * 128 + kc + kq * 4];
                As[(kq * 4 + 0) * 132 + m] = v.x;
                As[(kq * 4 + 1) * 132 + m] = v.y;
                As[(kq * 4 + 2) * 132 + m] = v.z;
                As[(kq * 4 + 3) * 132 + m] = v.w;
            }
#pragma unroll
            for (int i = 0; i < 4; i++) {
                int lin = t + i * 256;
                int k = lin >> 5, n4 = lin & 31;
                float4 v = *(const float4*)&Wp[(size_t)(kc + k) * 128 + n4 * 4];
                *(float4*)&Ws[k * 132 + n4 * 4] = v;
            }
            __syncthreads();
#pragma unroll 8
            for (int k = 0; k < 32; k++) {
                float4 a0 = *(const float4*)&As[k * 132 + ty * 8];
                float4 a1 = *(const float4*)&As[k * 132 + ty * 8 + 4];
                float4 b0 = *(const float4*)&Ws[k * 132 + tx * 8];
                float4 b1 = *(const float4*)&Ws[k * 132 + tx * 8 + 4];
                float a[8] = {a0.x, a0.y, a0.z, a0.w, a1.x, a1.y, a1.z, a1.w};
                float b[8] = {b0.x, b0.y, b0.z, b0.w, b1.x, b1.y, b1.z, b1.w};
#pragma unroll
                for (int i = 0; i < 8; i++)
#pragma unroll
                    for (int j = 0; j < 8; j++) c[i][j] = fmaf(a[i], b[j], c[i][j]);
            }
        }
    }

    float bv[8];
#pragma unroll
    for (int j = 0; j < 8; j++) bv[j] = bias ? bias[tx * 8 + j] : 0.f;

    float s1[8], s2[8];
#pragma unroll
    for (int j = 0; j < 8; j++) { s1[j] = 0.f; s2[j] = 0.f; }

#pragma unroll
    for (int i = 0; i < 8; i++) {
        size_t base = (size_t)(r0 + ty * 8 + i) * 128 + tx * 8;
        float v[8];
#pragma unroll
        for (int j = 0; j < 8; j++) {
            v[j] = c[i][j] + bv[j];
            s1[j] += v[j];
            s2[j] += v[j] * v[j];
        }
        *(float4*)&out[base]     = make_float4(v[0], v[1], v[2], v[3]);
        *(float4*)&out[base + 4] = make_float4(v[4], v[5], v[6], v[7]);
    }

    __syncthreads();
#pragma unroll
    for (int j = 0; j < 8; j++) {
        As[ty * 128 + tx * 8 + j] = s1[j];
        Ws[ty * 128 + tx * 8 + j] = s2[j];
    }
    __syncthreads();
    if (t < 128) {
        float S = 0.f, Q = 0.f;
#pragma unroll
        for (int g = 0; g < 16; g++) { S += As[g * 128 + t]; Q += Ws[g * 128 + t]; }
        g_psum[blockIdx.x * 128 + t] = S;
        g_psq [blockIdx.x * 128 + t] = Q;
    }
}

__global__ void colstat_final()
{
    const int t = threadIdx.x;
    float s = 0.f, s2 = 0.f;
    for (int b = 0; b < 256; b++) { s += g_psum[b * 128 + t]; s2 += g_psq[b * 128 + t]; }
    float m   = s / (float)MROWS;
    float var = s2 / (float)MROWS - m * m;
    g_mean[t] = m;
    g_rstd[t] = rsqrtf(var + EPSBN);
}

// ============ BN apply (mode 1: +GELU, mode 2: +residual) ============
__global__ void bn_apply(const float* __restrict__ X, const float* __restrict__ gamma,
                         const float* __restrict__ beta, const float* __restrict__ resid,
                         float* __restrict__ Y, int mode)
{
    const int i4 = blockIdx.x * blockDim.x + threadIdx.x;
    const size_t i = (size_t)i4 * 4;
    const int ch = (int)(i & 127);
    float4 v  = *(const float4*)&X[i];
    float4 ga = *(const float4*)&gamma[ch];
    float4 be = *(const float4*)&beta[ch];
    float4 mn = *(const float4*)&g_mean[ch];
    float4 rs = *(const float4*)&g_rstd[ch];
    float o[4];
    o[0] = ga.x * (v.x - mn.x) * rs.x + be.x;
    o[1] = ga.y * (v.y - mn.y) * rs.y + be.y;
    o[2] = ga.z * (v.z - mn.z) * rs.z + be.z;
    o[3] = ga.w * (v.w - mn.w) * rs.w + be.w;
    if (mode == 1) {
#pragma unroll
        for (int j = 0; j < 4; j++)
            o[j] = 0.5f * o[j] * (1.f + erff(o[j] * 0.70710678118654752f));
    } else if (mode == 2) {
        float4 r = *(const float4*)&resid[i];
        o[0] += r.x; o[1] += r.y; o[2] += r.z; o[3] += r.w;
    }
    *(float4*)&Y[i] = make_float4(o[0], o[1], o[2], o[3]);
}

// ===== BN apply + fp16 2-way split + row sq-norm (fc1 output), warp per row =====
__global__ void bn_split(const float* __restrict__ X, const float* __restrict__ gamma,
                         const float* __restrict__ beta, float* __restrict__ H,
                         __half* __restrict__ Hh, __half* __restrict__ Hm,
                         float* __restrict__ sqo)
{
    const int wid = threadIdx.x >> 5, lane = threadIdx.x & 31;
    const int row = blockIdx.x * 8 + wid;
    const int ch = lane * 4;
    const size_t base = (size_t)row * 128 + ch;
    float4 v  = *(const float4*)&X[base];
    float4 ga = *(const float4*)&gamma[ch];
    float4 be = *(const float4*)&beta[ch];
    float4 mn = *(const float4*)&g_mean[ch];
    float4 rs = *(const float4*)&g_rstd[ch];
    float o[4];
    o[0] = ga.x * (v.x - mn.x) * rs.x + be.x;
    o[1] = ga.y * (v.y - mn.y) * rs.y + be.y;
    o[2] = ga.z * (v.z - mn.z) * rs.z + be.z;
    o[3] = ga.w * (v.w - mn.w) * rs.w + be.w;
    *(float4*)&H[base] = make_float4(o[0], o[1], o[2], o[3]);

    __half hh[4], hm[4];
#pragma unroll
    for (int j = 0; j < 4; j++) {
        hh[j] = __float2half_rn(o[j]);
        hm[j] = __float2half_rn(o[j] - __half2float(hh[j]));
    }
    ((__half2*)(Hh + base))[0] = __halves2half2(hh[0], hh[1]);
    ((__half2*)(Hh + base))[1] = __halves2half2(hh[2], hh[3]);
    ((__half2*)(Hm + base))[0] = __halves2half2(hm[0], hm[1]);
    ((__half2*)(Hm + base))[1] = __halves2half2(hm[2], hm[3]);

    float s = o[0]*o[0] + o[1]*o[1] + o[2]*o[2] + o[3]*o[3];
#pragma unroll
    for (int off = 16; off; off >>= 1) s += __shfl_xor_sync(0xffffffffu, s, off);
    if (lane == 0) sqo[row] = s;
}

// =================================================================================
// KNN + max-relative aggregation via mma.sync fp16 2-split (3 products).
// 256 threads / 64 query rows per CTA, 2 CTAs per SM (independent streams overlap
// each other's barrier and cp.async stalls). Warp = 16-row strip x 32-col half.
// Register top-9 lists (unrolled compare-swap), with an 8-key min-tree guard so
// the insert machinery only runs when a key actually beats the threshold.
// =================================================================================
#define ROWB     272                 // padded fp16 row: 136 halves
#define QSPLIT   (64 * ROWB)         // 17408
#define QBYTES   (2 * QSPLIT)        // 34816
#define CBUF     (2 * QSPLIT)        // 34816 per ring slot (2 splits x 64 cands)
#define RING_OFF QBYTES              // 34816
#define SQN_OFF  (RING_OFF + 2 * CBUF)   // 104448 (2 slots x 256B)
#define KNN_SMEM (SQN_OFF + 512)         // 104960  (x2 CTAs = 209920 <= 227KB)
#define NT       64                  // 64-cand tiles

// 64 rows x 256B x 2 splits = 2048 cp16 ops, 256 threads -> 8 iters
__device__ __forceinline__ void loadT(uint32_t smdst,
                                      const __half* __restrict__ Hh,
                                      const __half* __restrict__ Hm,
                                      int rowBase, int t)
{
#pragma unroll
    for (int i = 0; i < 8; i++) {
        int lin = t + i * 256;            // [0,2048)
        int s = lin >> 10, rem = lin & 1023;
        int row = rem >> 4, ch = rem & 15;
        const __half* sp = s ? Hm : Hh;
        cp16(smdst + (uint32_t)(s * QSPLIT + row * ROWB + ch * 16),
             (const char*)(sp + (size_t)(rowBase + row) * 128) + ch * 16);
    }
}

// register insertion into sorted top-9 (strict <, stable for ascending-j feed)
#define INS9(Bst, Idx, KEY, J) do {                                        \
    float _k = (KEY); int _j = (J);                                        \
    if (_k < Bst[8]) {                                                     \
        float ck = _k; int cj = _j;                                        \
        _Pragma("unroll")                                                  \
        for (int _p = 0; _p < 9; _p++) {                                   \
            if (ck < Bst[_p]) {                                            \
                float tk = Bst[_p]; int tj = Idx[_p];                      \
                Bst[_p] = ck; Idx[_p] = cj; ck = tk; cj = tj;              \
            }                                                              \
        }                                                                  \
    }                                                                      \
} while (0)

__global__ __launch_bounds__(256, 2) void knn_mma(const __half* __restrict__ Hh,
                                                  const __half* __restrict__ Hm,
                                                  const float* __restrict__ h,
                                                  const float* __restrict__ sq,
                                                  float* __restrict__ agg)
{
    extern __shared__ __align__(16) char smp[];
    const uint32_t smb = smem_u32(smp);
    const int t = threadIdx.x, w = t >> 5, lane = t & 31;
    const int wr = w & 3;          // 16-row strip (of 64 rows)
    const int wc = w >> 2;         // 32-col half
    const int b = blockIdx.y, bOff = b * NPTS, r0 = blockIdx.x * 64;

    // prologue: Q resident + tile 0 into slot 0
    loadT(smb, Hh, Hm, bOff + r0, t);
    loadT(smb + RING_OFF, Hh, Hm, bOff, t);
    if (t < 16) cp16(smb + (uint32_t)(SQN_OFF + t * 16), (const char*)(sq + bOff) + t * 16);
    CP_COMMIT();
    CP_WAIT(0);
    __syncthreads();

    float bA[9], bB[9];
    int   iA[9], iB[9];
#pragma unroll
    for (int p = 0; p < 9; p++) { bA[p] = 3.0e38f; bB[p] = 3.0e38f; iA[p] = 0; iB[p] = 0; }
    float thrA = 3.0e38f, thrB = 3.0e38f;

    const uint32_t aoff = (uint32_t)((wr * 16 + (lane & 15)) * ROWB + ((lane >> 4) * 16));
    const uint32_t boff = (uint32_t)(((lane & 7) + ((lane & 16) ? 8 : 0)) * ROWB
                                     + ((lane & 8) ? 16 : 0));
    const int cq = 2 * (lane & 3);

    for (int ct = 0; ct < NT; ct++) {
        if (ct > 0) {
            CP_WAIT(0);        // tile ct resident
            __syncthreads();   // all warps done with tile ct-1 -> its slot is free
        }
        if (ct + 1 < NT) {
            loadT(smb + (uint32_t)(RING_OFF + ((ct + 1) & 1) * CBUF), Hh, Hm,
                  bOff + (ct + 1) * 64, t);
            if (t < 16) cp16(smb + (uint32_t)(SQN_OFF + ((ct + 1) & 1) * 256 + t * 16),
                             (const char*)(sq + bOff + (ct + 1) * 64) + t * 16);
            CP_COMMIT();
        }

        const uint32_t cb = smb + (uint32_t)(RING_OFF + (ct & 1) * CBUF)
                          + (uint32_t)(wc * 32 * ROWB);

        float acc[4][4];
#pragma unroll
        for (int n8 = 0; n8 < 4; n8++)
#pragma unroll
            for (int q = 0; q < 4; q++) acc[n8][q] = 0.f;

#pragma unroll
        for (int ks = 0; ks < 8; ks++) {
            uint32_t Af0[4], Af1[4];
            ldsm4(Af0, smb + (uint32_t)(ks * 32) + aoff);
            ldsm4(Af1, smb + (uint32_t)(QSPLIT + ks * 32) + aoff);
            uint32_t Bf[2][2][4];
#pragma unroll
            for (int np = 0; np < 2; np++)
#pragma unroll
                for (int s = 0; s < 2; s++)
                    ldsm4(Bf[np][s], cb + (uint32_t)(s * QSPLIT + np * 16 * ROWB + ks * 32) + boff);
#pragma unroll
            for (int np = 0; np < 2; np++) {
                mma16816h(acc[np * 2 + 0], Af0, Bf[np][0][0], Bf[np][0][1]);   // hh
                mma16816h(acc[np * 2 + 1], Af0, Bf[np][0][2], Bf[np][0][3]);
            }
#pragma unroll
            for (int np = 0; np < 2; np++) {
                mma16816h(acc[np * 2 + 0], Af0, Bf[np][1][0], Bf[np][1][1]);   // h*m
                mma16816h(acc[np * 2 + 1], Af0, Bf[np][1][2], Bf[np][1][3]);
            }
#pragma unroll
            for (int np = 0; np < 2; np++) {
                mma16816h(acc[np * 2 + 0], Af1, Bf[np][0][0], Bf[np][0][1]);   // m*h
                mma16816h(acc[np * 2 + 1], Af1, Bf[np][0][2], Bf[np][0][3]);
            }
        }

        // keys: sq[j] - 2*dot; min-guard the insert machinery (rare path)
        const float* sqt = (const float*)(smp + SQN_OFF + (ct & 1) * 256) + wc * 32;
        const int jg0 = ct * 64 + wc * 32;
        float kA[8], kB[8];
#pragma unroll
        for (int n8 = 0; n8 < 4; n8++) {
            float s0 = sqt[n8 * 8 + cq];
            float s1 = sqt[n8 * 8 + cq + 1];
            kA[n8 * 2 + 0] = fmaf(-2.f, acc[n8][0], s0);
            kA[n8 * 2 + 1] = fmaf(-2.f, acc[n8][1], s1);
            kB[n8 * 2 + 0] = fmaf(-2.f, acc[n8][2], s0);
            kB[n8 * 2 + 1] = fmaf(-2.f, acc[n8][3], s1);
        }
        float mA = fminf(fminf(fminf(kA[0], kA[1]), fminf(kA[2], kA[3])),
                         fminf(fminf(kA[4], kA[5]), fminf(kA[6], kA[7])));
        float mB = fminf(fminf(fminf(kB[0], kB[1]), fminf(kB[2], kB[3])),
                         fminf(fminf(kB[4], kB[5]), fminf(kB[6], kB[7])));
        if (mA < thrA) {
#pragma unroll
            for (int q = 0; q < 8; q++) {
                int j = jg0 + (q >> 1) * 8 + cq + (q & 1);
                INS9(bA, iA, kA[q], j);
            }
            thrA = bA[8];
        }
        if (mB < thrB) {
#pragma unroll
            for (int q = 0; q < 8; q++) {
                int j = jg0 + (q >> 1) * 8 + cq + (q & 1);
                INS9(bB, iB, kB[q], j);
            }
            thrB = bB[8];
        }
    }

    // ---- merge per-row candidates: 8 contributors x 9 -> top-9 per row ----
    __syncthreads();
    float* ckey = (float*)smp;                      // [64][72]
    int*   cidx = (int*)(smp + 64 * 72 * 4);        // [64][72]
    int*   nbx  = (int*)(smp + 2 * 64 * 72 * 4);    // [64][9]
    {
        const int rA = wr * 16 + (lane >> 2);
        const int rB = rA + 8;
        const int sl = (wc * 4 + (lane & 3)) * 9;
#pragma unroll
        for (int p = 0; p < 9; p++) {
            ckey[rA * 72 + sl + p] = bA[p];  cidx[rA * 72 + sl + p] = iA[p];
            ckey[rB * 72 + sl + p] = bB[p];  cidx[rB * 72 + sl + p] = iB[p];
        }
    }
    __syncthreads();

    if (t < 64) {
        float bk[9]; int bj[9];
#pragma unroll
        for (int p = 0; p < 9; p++) { bk[p] = 3.0e38f; bj[p] = 0x7fffffff; }
        for (int q = 0; q < 72; q++) {
            float k = ckey[t * 72 + q];
            int   j = cidx[t * 72 + q];
            if (k < bk[8] || (k == bk[8] && j < bj[8])) {
                float ck = k; int cj = j;
#pragma unroll
                for (int p = 0; p < 9; p++) {
                    if (ck < bk[p] || (ck == bk[p] && cj < bj[p])) {
                        float tk = bk[p]; int tj = bj[p];
                        bk[p] = ck; bj[p] = cj; ck = tk; cj = tj;
                    }
                }
            }
        }
#pragma unroll
        for (int p = 0; p < 9; p++) nbx[t * 9 + p] = bj[p];
    }
    __syncthreads();

    // ---- cooperative gather + max-relative aggregation (warp per 8 rows) ----
    for (int rr = 0; rr < 8; rr++) {
        const int row = w * 8 + rr;
        float4 q = *(const float4*)&h[(size_t)(bOff + r0 + row) * 128 + lane * 4];
        float m0 = -3.0e38f, m1 = -3.0e38f, m2 = -3.0e38f, m3 = -3.0e38f;
#pragma unroll
        for (int p = 0; p < KTOP; p++) {
            int j = nbx[row * 9 + p];
            float4 v = *(const float4*)&h[(size_t)(bOff + j) * 128 + lane * 4];
            m0 = fmaxf(m0, v.x); m1 = fmaxf(m1, v.y);
            m2 = fmaxf(m2, v.z); m3 = fmaxf(m3, v.w);
        }
        *(float4*)&agg[(size_t)(bOff + r0 + row) * 128 + lane * 4] =
            make_float4(m0 - q.x, m1 - q.y, m2 - q.z, m3 - q.w);
    }
}

// =================================================================================
// Launch sequence
// =================================================================================
extern "C" void kernel_launch(void* const* d_in, const int* in_sizes, int n_in,
                              void* d_out, int out_size)
{
    const float* x   = (const float*)d_in[0];
    const float* W1  = (const float*)d_in[1];
    const float* b1  = (const float*)d_in[2];
    const float* g1  = (const float*)d_in[3];
    const float* be1 = (const float*)d_in[4];
    const float* Wg  = (const float*)d_in[5];
    const float* bg  = (const float*)d_in[6];
    const float* gg  = (const float*)d_in[7];
    const float* beg = (const float*)d_in[8];
    const float* W2  = (const float*)d_in[9];
    const float* b2  = (const float*)d_in[10];
    const float* g2  = (const float*)d_in[11];
    const float* be2 = (const float*)d_in[12];
    float* out = (float*)d_out;

    float *ph, *pagg, *pt2, *psq;
    __half *phh, *phm;
    cudaGetSymbolAddress((void**)&ph,   g_h);
    cudaGetSymbolAddress((void**)&pagg, g_agg);
    cudaGetSymbolAddress((void**)&pt2,  g_t2);
    cudaGetSymbolAddress((void**)&psq,  g_sq);
    cudaGetSymbolAddress((void**)&phh,  g_hh);
    cudaGetSymbolAddress((void**)&phm,  g_hm);

    cudaFuncSetAttribute(knn_mma, cudaFuncAttributeMaxDynamicSharedMemorySize, KNN_SMEM);

    // fc1 (+fused stats) + BN/split/norms
    gemm128<<<256, 256>>>(x, nullptr, W1, b1, ph);
    colstat_final<<<1, 128>>>();
    bn_split<<<4096, 256>>>(ph, g1, be1, ph, phh, phm, psq);

    // KNN + max-relative aggregation (tensor cores via mma.sync, fp16 2-split)
    knn_mma<<<dim3(64, 8), 256, KNN_SMEM>>>(phh, phm, ph, psq, pagg);

    // graph conv MLP: cat([h, agg]) @ Wg + bg (single fused 256-K GEMM), BN, GELU
    gemm128<<<256, 256>>>(ph, pagg, Wg, bg, pt2);
    colstat_final<<<1, 128>>>();
    bn_apply<<<4096, 256>>>(pt2, gg, beg, nullptr, pt2, 1);

    // fc2 (+fused stats) + BN + residual
    gemm128<<<256, 256>>>(pt2, nullptr, W2, b2, out);
    colstat_final<<<1, 128>>>();
    bn_apply<<<4096, 256>>>(out, g2, be2, x, out, 2);
}

// round 16
// speedup vs baseline: 1.7672x; 1.0218x over previous
#include <cuda_runtime.h>
#include <cuda_fp16.h>
#include <math.h>
#include <stdint.h>

// Problem constants
#define BSZ   8
#define NPTS  4096
#define CDIM  128
#define KTOP  9
#define MROWS (BSZ * NPTS)   // 32768
#define EPSBN 1e-5f

// ---------------- scratch (device globals; no allocation allowed) ----------------
__device__ float g_h  [MROWS * CDIM];
__device__ float g_agg[MROWS * CDIM];
__device__ float g_t2 [MROWS * CDIM];
__device__ float g_sq [MROWS];
__device__ __half g_hh[MROWS * CDIM];   // fp16 hi split of h
__device__ __half g_hm[MROWS * CDIM];   // fp16 mid split (residual)
__device__ float g_psum[256 * 128];
__device__ float g_psq [256 * 128];
__device__ float g_mean[128];
__device__ float g_rstd[128];

// =================================================================================
// PTX helpers (baseline sm_80+ ISA only: ldmatrix / mma.sync / cp.async)
// =================================================================================
__device__ __forceinline__ uint32_t smem_u32(const void* p) {
    uint32_t a;
    asm("{ .reg .u64 t; cvta.to.shared.u64 t, %1; cvt.u32.u64 %0, t; }" : "=r"(a) : "l"(p));
    return a;
}
__device__ __forceinline__ void ldsm4(uint32_t* r, uint32_t a) {
    asm volatile("ldmatrix.sync.aligned.m8n8.x4.shared.b16 {%0,%1,%2,%3}, [%4];"
                 : "=r"(r[0]), "=r"(r[1]), "=r"(r[2]), "=r"(r[3]) : "r"(a));
}
__device__ __forceinline__ void mma16816h(float* c, const uint32_t* a, uint32_t b0, uint32_t b1) {
    asm volatile("mma.sync.aligned.m16n8k16.row.col.f32.f16.f16.f32 "
                 "{%0,%1,%2,%3},{%4,%5,%6,%7},{%8,%9},{%0,%1,%2,%3};"
                 : "+f"(c[0]), "+f"(c[1]), "+f"(c[2]), "+f"(c[3])
                 : "r"(a[0]), "r"(a[1]), "r"(a[2]), "r"(a[3]), "r"(b0), "r"(b1));
}
__device__ __forceinline__ void cp16(uint32_t dst, const void* src) {
    asm volatile("cp.async.cg.shared.global [%0], [%1], 16;" :: "r"(dst), "l"(src));
}
#define CP_COMMIT() asm volatile("cp.async.commit_group;" ::: "memory")
#define CP_WAIT(n)  asm volatile("cp.async.wait_group %0;" :: "n"(n) : "memory")

// =================================================================================
// Tiled SGEMM: out[M x 128] = A[M x 128] @ W (+ A2 @ W[128:]) + bias.
// Fused deterministic column stats (sum / sumsq) into the epilogue.
// =================================================================================
__global__ __launch_bounds__(256) void gemm128(const float* __restrict__ A,
                                               const float* __restrict__ A2,
                                               const float* __restrict__ W,
                                               const float* __restrict__ bias,
                                               float* __restrict__ out)
{
    __shared__ float As[32 * 132];
    __shared__ float Ws[32 * 132];
    const int t  = threadIdx.x;
    const int tx = t & 15, ty = t >> 4;
    const int r0 = blockIdx.x * 128;

    float c[8][8];
#pragma unroll
    for (int i = 0; i < 8; i++)
#pragma unroll
        for (int j = 0; j < 8; j++) c[i][j] = 0.f;

    const int nSrc = A2 ? 2 : 1;
    for (int si = 0; si < nSrc; si++) {
        const float* Ap = si ? A2 : A;
        const float* Wp = W + si * 128 * 128;
        for (int kc = 0; kc < 128; kc += 32) {
            __syncthreads();
#pragma unroll
            for (int i = 0; i < 4; i++) {
                int lin = t + i * 256;
                int m = lin >> 3, kq = lin & 7;
                float4 v = *(const float4*)&Ap[(size_t)(r0 + m) * 128 + kc + kq * 4];
                As[(kq * 4 + 0) * 132 + m] = v.x;
                As[(kq * 4 + 1) * 132 + m] = v.y;
                As[(kq * 4 + 2) * 132 + m] = v.z;
                As[(kq * 4 + 3) * 132 + m] = v.w;
            }
#pragma unroll
            for (int i = 0; i < 4; i++) {
                int lin = t + i * 256;
                int k = lin >> 5, n4 = lin & 31;
                float4 v = *(const float4*)&Wp[(size_t)(kc + k) * 128 + n4 * 4];
                *(float4*)&Ws[k * 132 + n4 * 4] = v;
            }
            __syncthreads();
#pragma unroll 8
            for (int k = 0; k < 32; k++) {
                float4 a0 = *(const float4*)&As[k * 132 + ty * 8];
                float4 a1 = *(const float4*)&As[k * 132 + ty * 8 + 4];
                float4 b0 = *(const float4*)&Ws[k * 132 + tx * 8];
                float4 b1 = *(const float4*)&Ws[k * 132 + tx * 8 + 4];
                float a[8] = {a0.x, a0.y, a0.z, a0.w, a1.x, a1.y, a1.z, a1.w};
                float b[8] = {b0.x, b0.y, b0.z, b0.w, b1.x, b1.y, b1.z, b1.w};
#pragma unroll
                for (int i = 0; i < 8; i++)
#pragma unroll
                    for (int j = 0; j < 8; j++) c[i][j] = fmaf(a[i], b[j], c[i][j]);
            }
        }
    }

    float bv[8];
#pragma unroll
    for (int j = 0; j < 8; j++) bv[j] = bias ? bias[tx * 8 + j] : 0.f;

    float s1[8], s2[8];
#pragma unroll
    for (int j = 0; j < 8; j++) { s1[j] = 0.f; s2[j] = 0.f; }

#pragma unroll
    for (int i = 0; i < 8; i++) {
        size_t base = (size_t)(r0 + ty * 8 + i) * 128 + tx * 8;
        float v[8];
#pragma unroll
        for (int j = 0; j < 8; j++) {
            v[j] = c[i][j] + bv[j];
            s1[j] += v[j];
            s2[j] += v[j] * v[j];
        }
        *(float4*)&out[base]     = make_float4(v[0], v[1], v[2], v[3]);
        *(float4*)&out[base + 4] = make_float4(v[4], v[5], v[6], v[7]);
    }

    __syncthreads();
#pragma unroll
    for (int j = 0; j < 8; j++) {
        As[ty * 128 + tx * 8 + j] = s1[j];
        Ws[ty * 128 + tx * 8 + j] = s2[j];
    }
    __syncthreads();
    if (t < 128) {
        float S = 0.f, Q = 0.f;
#pragma unroll
        for (int g = 0; g < 16; g++) { S += As[g * 128 + t]; Q += Ws[g * 128 + t]; }
        g_psum[blockIdx.x * 128 + t] = S;
        g_psq [blockIdx.x * 128 + t] = Q;
    }
}

__global__ void colstat_final()
{
    const int t = threadIdx.x;
    float s = 0.f, s2 = 0.f;
    for (int b = 0; b < 256; b++) { s += g_psum[b * 128 + t]; s2 += g_psq[b * 128 + t]; }
    float m   = s / (float)MROWS;
    float var = s2 / (float)MROWS - m * m;
    g_mean[t] = m;
    g_rstd[t] = rsqrtf(var + EPSBN);
}

// ============ BN apply (mode 1: +GELU, mode 2: +residual) ============
__global__ void bn_apply(const float* __restrict__ X, const float* __restrict__ gamma,
                         const float* __restrict__ beta, const float* __restrict__ resid,
                         float* __restrict__ Y, int mode)
{
    const int i4 = blockIdx.x * blockDim.x + threadIdx.x;
    const size_t i = (size_t)i4 * 4;
    const int ch = (int)(i & 127);
    float4 v  = *(const float4*)&X[i];
    float4 ga = *(const float4*)&gamma[ch];
    float4 be = *(const float4*)&beta[ch];
    float4 mn = *(const float4*)&g_mean[ch];
    float4 rs = *(const float4*)&g_rstd[ch];
    float o[4];
    o[0] = ga.x * (v.x - mn.x) * rs.x + be.x;
    o[1] = ga.y * (v.y - mn.y) * rs.y + be.y;
    o[2] = ga.z * (v.z - mn.z) * rs.z + be.z;
    o[3] = ga.w * (v.w - mn.w) * rs.w + be.w;
    if (mode == 1) {
#pragma unroll
        for (int j = 0; j < 4; j++)
            o[j] = 0.5f * o[j] * (1.f + erff(o[j] * 0.70710678118654752f));
    } else if (mode == 2) {
        float4 r = *(const float4*)&resid[i];
        o[0] += r.x; o[1] += r.y; o[2] += r.z; o[3] += r.w;
    }
    *(float4*)&Y[i] = make_float4(o[0], o[1], o[2], o[3]);
}

// ===== BN apply + fp16 2-way split + row sq-norm (fc1 output), warp per row =====
__global__ void bn_split(const float* __restrict__ X, const float* __restrict__ gamma,
                         const float* __restrict__ beta, float* __restrict__ H,
                         __half* __restrict__ Hh, __half* __restrict__ Hm,
                         float* __restrict__ sqo)
{
    const int wid = threadIdx.x >> 5, lane = threadIdx.x & 31;
    const int row = blockIdx.x * 8 + wid;
    const int ch = lane * 4;
    const size_t base = (size_t)row * 128 + ch;
    float4 v  = *(const float4*)&X[base];
    float4 ga = *(const float4*)&gamma[ch];
    float4 be = *(const float4*)&beta[ch];
    float4 mn = *(const float4*)&g_mean[ch];
    float4 rs = *(const float4*)&g_rstd[ch];
    float o[4];
    o[0] = ga.x * (v.x - mn.x) * rs.x + be.x;
    o[1] = ga.y * (v.y - mn.y) * rs.y + be.y;
    o[2] = ga.z * (v.z - mn.z) * rs.z + be.z;
    o[3] = ga.w * (v.w - mn.w) * rs.w + be.w;
    *(float4*)&H[base] = make_float4(o[0], o[1], o[2], o[3]);

    __half hh[4], hm[4];
#pragma unroll
    for (int j = 0; j < 4; j++) {
        hh[j] = __float2half_rn(o[j]);
        hm[j] = __float2half_rn(o[j] - __half2float(hh[j]));
    }
    ((__half2*)(Hh + base))[0] = __halves2half2(hh[0], hh[1]);
    ((__half2*)(Hh + base))[1] = __halves2half2(hh[2], hh[3]);
    ((__half2*)(Hm + base))[0] = __halves2half2(hm[0], hm[1]);
    ((__half2*)(Hm + base))[1] = __halves2half2(hm[2], hm[3]);

    float s = o[0]*o[0] + o[1]*o[1] + o[2]*o[2] + o[3]*o[3];
#pragma unroll
    for (int off = 16; off; off >>= 1) s += __shfl_xor_sync(0xffffffffu, s, off);
    if (lane == 0) sqo[row] = s;
}

// =================================================================================
// KNN + max-relative aggregation via mma.sync fp16 2-split (3 products).
// 256 threads / 64 query rows per CTA, 2 CTAs per SM. Warp = 16-row strip x
// 32-col half. Register top-9 with min-tree guard. Tile loads use fully
// strength-reduced addressing: per-thread (row0,ch) constants + running global
// pointers, immediate smem offsets.
// =================================================================================
#define ROWB     272                 // padded fp16 row: 136 halves
#define QSPLIT   (64 * ROWB)         // 17408
#define QBYTES   (2 * QSPLIT)        // 34816
#define CBUF     (2 * QSPLIT)        // 34816 per ring slot (2 splits x 64 cands)
#define RING_OFF QBYTES              // 34816
#define SQN_OFF  (RING_OFF + 2 * CBUF)   // 104448 (2 slots x 256B)
#define KNN_SMEM (SQN_OFF + 512)         // 104960  (x2 CTAs = 209920 <= 227KB)
#define NT       64                  // 64-cand tiles
#define TILEB    16384               // global bytes per 64-row split tile

// 8 cp16 per thread, addresses: base + {0,4096,8192,12288} per split
__device__ __forceinline__ void loadT2(uint32_t dstBase, const char* srcH, const char* srcM)
{
#pragma unroll
    for (int i = 0; i < 4; i++) {
        cp16(dstBase + (uint32_t)(i * 16 * ROWB), srcH + i * 4096);
        cp16(dstBase + (uint32_t)(QSPLIT + i * 16 * ROWB), srcM + i * 4096);
    }
}

// register insertion into sorted top-9 (strict <, stable for ascending-j feed)
#define INS9(Bst, Idx, KEY, J) do {                                        \
    float _k = (KEY); int _j = (J);                                        \
    if (_k < Bst[8]) {                                                     \
        float ck = _k; int cj = _j;                                        \
        _Pragma("unroll")                                                  \
        for (int _p = 0; _p < 9; _p++) {                                   \
            if (ck < Bst[_p]) {                                            \
                float tk = Bst[_p]; int tj = Idx[_p];                      \
                Bst[_p] = ck; Idx[_p] = cj; ck = tk; cj = tj;              \
            }                                                              \
        }                                                                  \
    }                                                                      \
} while (0)

__global__ __launch_bounds__(256, 2) void knn_mma(const __half* __restrict__ Hh,
                                                  const __half* __restrict__ Hm,
                                                  const float* __restrict__ h,
                                                  const float* __restrict__ sq,
                                                  float* __restrict__ agg)
{
    extern __shared__ __align__(16) char smp[];
    const uint32_t smb = smem_u32(smp);
    const int t = threadIdx.x, w = t >> 5, lane = t & 31;
    const int wr = w & 3;          // 16-row strip (of 64 rows)
    const int wc = w >> 2;         // 32-col half
    const int b = blockIdx.y, bOff = b * NPTS, r0 = blockIdx.x * 64;

    // strength-reduced load addressing (per-thread constants)
    const int chB  = (t & 15) * 16;             // byte offset within 256B row
    const int row0 = t >> 4;                    // 0..15
    const uint32_t dstOff = (uint32_t)(row0 * ROWB + chB);
    const size_t thrOff = (size_t)row0 * 256 + chB;

    // prologue: Q resident + tile 0 into slot 0
    loadT2(smb + dstOff,
           (const char*)Hh + (size_t)(bOff + r0) * 256 + thrOff,
           (const char*)Hm + (size_t)(bOff + r0) * 256 + thrOff);
    const char* nH = (const char*)Hh + (size_t)bOff * 256 + thrOff;  // next tile src
    const char* nM = (const char*)Hm + (size_t)bOff * 256 + thrOff;
    loadT2(smb + RING_OFF + dstOff, nH, nM);
    nH += TILEB; nM += TILEB;
    if (t < 16) cp16(smb + (uint32_t)(SQN_OFF + t * 16), (const char*)(sq + bOff) + t * 16);
    CP_COMMIT();
    CP_WAIT(0);
    __syncthreads();

    float bA[9], bB[9];
    int   iA[9], iB[9];
#pragma unroll
    for (int p = 0; p < 9; p++) { bA[p] = 3.0e38f; bB[p] = 3.0e38f; iA[p] = 0; iB[p] = 0; }
    float thrA = 3.0e38f, thrB = 3.0e38f;

    const uint32_t aoff = (uint32_t)((wr * 16 + (lane & 15)) * ROWB + ((lane >> 4) * 16));
    const uint32_t boff = (uint32_t)(((lane & 7) + ((lane & 16) ? 8 : 0)) * ROWB
                                     + ((lane & 8) ? 16 : 0));
    const int cq = 2 * (lane & 3);
    const int jlane = wc * 32 + cq;             // lane-constant part of j

    for (int ct = 0; ct < NT; ct++) {
        if (ct > 0) {
            CP_WAIT(0);        // tile ct resident
            __syncthreads();   // all warps done with tile ct-1 -> its slot is free
        }
        if (ct + 1 < NT) {
            loadT2(smb + (uint32_t)(RING_OFF + ((ct + 1) & 1) * CBUF) + dstOff, nH, nM);
            nH += TILEB; nM += TILEB;
            if (t < 16) cp16(smb + (uint32_t)(SQN_OFF + ((ct + 1) & 1) * 256 + t * 16),
                             (const char*)(sq + bOff + (ct + 1) * 64) + t * 16);
            CP_COMMIT();
        }

        const uint32_t cb = smb + (uint32_t)(RING_OFF + (ct & 1) * CBUF)
                          + (uint32_t)(wc * 32 * ROWB);

        float acc[4][4];
#pragma unroll
        for (int n8 = 0; n8 < 4; n8++)
#pragma unroll
            for (int q = 0; q < 4; q++) acc[n8][q] = 0.f;

#pragma unroll
        for (int ks = 0; ks < 8; ks++) {
            uint32_t Af0[4], Af1[4];
            ldsm4(Af0, smb + (uint32_t)(ks * 32) + aoff);
            ldsm4(Af1, smb + (uint32_t)(QSPLIT + ks * 32) + aoff);
            uint32_t Bf[2][2][4];
#pragma unroll
            for (int np = 0; np < 2; np++)
#pragma unroll
                for (int s = 0; s < 2; s++)
                    ldsm4(Bf[np][s], cb + (uint32_t)(s * QSPLIT + np * 16 * ROWB + ks * 32) + boff);
#pragma unroll
            for (int np = 0; np < 2; np++) {
                mma16816h(acc[np * 2 + 0], Af0, Bf[np][0][0], Bf[np][0][1]);   // hh
                mma16816h(acc[np * 2 + 1], Af0, Bf[np][0][2], Bf[np][0][3]);
            }
#pragma unroll
            for (int np = 0; np < 2; np++) {
                mma16816h(acc[np * 2 + 0], Af0, Bf[np][1][0], Bf[np][1][1]);   // h*m
                mma16816h(acc[np * 2 + 1], Af0, Bf[np][1][2], Bf[np][1][3]);
            }
#pragma unroll
            for (int np = 0; np < 2; np++) {
                mma16816h(acc[np * 2 + 0], Af1, Bf[np][0][0], Bf[np][0][1]);   // m*h
                mma16816h(acc[np * 2 + 1], Af1, Bf[np][0][2], Bf[np][0][3]);
            }
        }

        // keys: sq[j] - 2*dot; min-guard the insert machinery (rare path)
        const float* sqt = (const float*)(smp + SQN_OFF + (ct & 1) * 256) + wc * 32;
        const int jg0 = ct * 64 + jlane;
        float kA[8], kB[8];
#pragma unroll
        for (int n8 = 0; n8 < 4; n8++) {
            float s0 = sqt[n8 * 8 + cq];
            float s1 = sqt[n8 * 8 + cq + 1];
            kA[n8 * 2 + 0] = fmaf(-2.f, acc[n8][0], s0);
            kA[n8 * 2 + 1] = fmaf(-2.f, acc[n8][1], s1);
            kB[n8 * 2 + 0] = fmaf(-2.f, acc[n8][2], s0);
            kB[n8 * 2 + 1] = fmaf(-2.f, acc[n8][3], s1);
        }
        float mA = fminf(fminf(fminf(kA[0], kA[1]), fminf(kA[2], kA[3])),
                         fminf(fminf(kA[4], kA[5]), fminf(kA[6], kA[7])));
        float mB = fminf(fminf(fminf(kB[0], kB[1]), fminf(kB[2], kB[3])),
                         fminf(fminf(kB[4], kB[5]), fminf(kB[6], kB[7])));
        if (mA < thrA) {
#pragma unroll
            for (int q = 0; q < 8; q++) {
                int j = jg0 + (q >> 1) * 8 + (q & 1);
                INS9(bA, iA, kA[q], j);
            }
            thrA = bA[8];
        }
        if (mB < thrB) {
#pragma unroll
            for (int q = 0; q < 8; q++) {
                int j = jg0 + (q >> 1) * 8 + (q & 1);
                INS9(bB, iB, kB[q], j);
            }
            thrB = bB[8];
        }
    }

    // ---- merge per-row candidates: 8 contributors x 9 -> top-9 per row ----
    __syncthreads();
    float* ckey = (float*)smp;                      // [64][72]
    int*   cidx = (int*)(smp + 64 * 72 * 4);        // [64][72]
    int*   nbx  = (int*)(smp + 2 * 64 * 72 * 4);    // [64][9]
    {
        const int rA = wr * 16 + (lane >> 2);
        const int rB = rA + 8;
        const int sl = (wc * 4 + (lane & 3)) * 9;
#pragma unroll
        for (int p = 0; p < 9; p++) {
            ckey[rA * 72 + sl + p] = bA[p];  cidx[rA * 72 + sl + p] = iA[p];
            ckey[rB * 72 + sl + p] = bB[p];  cidx[rB * 72 + sl + p] = iB[p];
        }
    }
    __syncthreads();

    if (t < 64) {
        float bk[9]; int bj[9];
#pragma unroll
        for (int p = 0; p < 9; p++) { bk[p] = 3.0e38f; bj[p] = 0x7fffffff; }
        for (int q = 0; q < 72; q++) {
            float k = ckey[t * 72 + q];
            int   j = cidx[t * 72 + q];
            if (k < bk[8] || (k == bk[8] && j < bj[8])) {
                float ck = k; int cj = j;
#pragma unroll
                for (int p = 0; p < 9; p++) {
                    if (ck < bk[p] || (ck == bk[p] && cj < bj[p])) {
                        float tk = bk[p]; int tj = bj[p];
                        bk[p] = ck; bj[p] = cj; ck = tk; cj = tj;
                    }
                }
            }
        }
#pragma unroll
        for (int p = 0; p < 9; p++) nbx[t * 9 + p] = bj[p];
    }
    __syncthreads();

    // ---- cooperative gather + max-relative aggregation (warp per 8 rows) ----
    for (int rr = 0; rr < 8; rr++) {
        const int row = w * 8 + rr;
        float4 q = *(const float4*)&h[(size_t)(bOff + r0 + row) * 128 + lane * 4];
        float m0 = -3.0e38f, m1 = -3.0e38f, m2 = -3.0e38f, m3 = -3.0e38f;
#pragma unroll
        for (int p = 0; p < KTOP; p++) {
            int j = nbx[row * 9 + p];
            float4 v = *(const float4*)&h[(size_t)(bOff + j) * 128 + lane * 4];
            m0 = fmaxf(m0, v.x); m1 = fmaxf(m1, v.y);
            m2 = fmaxf(m2, v.z); m3 = fmaxf(m3, v.w);
        }
        *(float4*)&agg[(size_t)(bOff + r0 + row) * 128 + lane * 4] =
            make_float4(m0 - q.x, m1 - q.y, m2 - q.z, m3 - q.w);
    }
}

// =================================================================================
// Launch sequence
// =================================================================================
extern "C" void kernel_launch(void* const* d_in, const int* in_sizes, int n_in,
                              void* d_out, int out_size)
{
    const float* x   = (const float*)d_in[0];
    const float* W1  = (const float*)d_in[1];
    const float* b1  = (const float*)d_in[2];
    const float* g1  = (const float*)d_in[3];
    const float* be1 = (const float*)d_in[4];
    const float* Wg  = (const float*)d_in[5];
    const float* bg  = (const float*)d_in[6];
    const float* gg  = (const float*)d_in[7];
    const float* beg = (const float*)d_in[8];
    const float* W2  = (const float*)d_in[9];
    const float* b2  = (const float*)d_in[10];
    const float* g2  = (const float*)d_in[11];
    const float* be2 = (const float*)d_in[12];
    float* out = (float*)d_out;

    float *ph, *pagg, *pt2, *psq;
    __half *phh, *phm;
    cudaGetSymbolAddress((void**)&ph,   g_h);
    cudaGetSymbolAddress((void**)&pagg, g_agg);
    cudaGetSymbolAddress((void**)&pt2,  g_t2);
    cudaGetSymbolAddress((void**)&psq,  g_sq);
    cudaGetSymbolAddress((void**)&phh,  g_hh);
    cudaGetSymbolAddress((void**)&phm,  g_hm);

    cudaFuncSetAttribute(knn_mma, cudaFuncAttributeMaxDynamicSharedMemorySize, KNN_SMEM);

    // fc1 (+fused stats) + BN/split/norms
    gemm128<<<256, 256>>>(x, nullptr, W1, b1, ph);
    colstat_final<<<1, 128>>>();
    bn_split<<<4096, 256>>>(ph, g1, be1, ph, phh, phm, psq);

    // KNN + max-relative aggregation (tensor cores via mma.sync, fp16 2-split)
    knn_mma<<<dim3(64, 8), 256, KNN_SMEM>>>(phh, phm, ph, psq, pagg);

    // graph conv MLP: cat([h, agg]) @ Wg + bg (single fused 256-K GEMM), BN, GELU
    gemm128<<<256, 256>>>(ph, pagg, Wg, bg, pt2);
    colstat_final<<<1, 128>>>();
    bn_apply<<<4096, 256>>>(pt2, gg, beg, nullptr, pt2, 1);

    // fc2 (+fused stats) + BN + residual
    gemm128<<<256, 256>>>(pt2, nullptr, W2, b2, out);
    colstat_final<<<1, 128>>>();
    bn_apply<<<4096, 256>>>(out, g2, be2, x, out, 2);
}